// round 1
// baseline (speedup 1.0000x reference)
#include <cuda_runtime.h>
#include <math.h>

#define B 64
#define S 4096
#define E 512
#define D 512
#define H 512
#define NEGV (-1.0e9f)

// Deterministic scratch (no cudaMalloc allowed)
__device__ float g_decoded[B * H];            // 128 KB
__device__ float g_attn_part[B * 32 * E];     // 4 MB

// ---------------------------------------------------------------------------
// Kernel 1: decoded[b,h] = sum_d dec[b,d] * W_dec[d,h]
// ---------------------------------------------------------------------------
__global__ void decode_kernel(const float* __restrict__ dec,
                              const float* __restrict__ W_dec) {
    int b = blockIdx.x;
    int t = threadIdx.x;  // 512 threads, t = h
    __shared__ float ds[D];
    ds[t] = dec[b * D + t];
    __syncthreads();
    float sum = 0.f;
#pragma unroll 8
    for (int d = 0; d < D; d++) sum += ds[d] * W_dec[d * H + t];
    g_decoded[b * H + t] = sum;
}

// ---------------------------------------------------------------------------
// Kernel 2: logits[b,s] = sum_h tanh( enc[b,s,:]@W_enc[:,h] + decoded[b,h] ) * W_out[h]
// Block tile: 64 rows (one b, one s-tile) x full H (in 4 chunks of 128).
// 256 threads, thread tile 4(M) x 8(N). Deterministic (no atomics).
// ---------------------------------------------------------------------------
#define MT 64
#define NT 128
#define KC 16

__global__ void __launch_bounds__(256, 3) logits_kernel(
    const float* __restrict__ enc, const float* __restrict__ W_enc,
    const float* __restrict__ W_out, float* __restrict__ logits) {
    __shared__ float a_s[KC][MT];   // [k][m]
    __shared__ float b_s[KC][NT];   // [k][n]

    int tid = threadIdx.x;
    int ty = tid >> 4;       // 0..15 -> 4 rows each
    int tx = tid & 15;       // 0..15 -> 8 cols each
    int b  = blockIdx.x >> 6;
    int st = blockIdx.x & 63;
    long base = (long)b * S + (long)st * MT;       // global row index
    const float* encBase = enc + base * E;

    // A-load mapping: thread -> (row, 4 consecutive k)
    int lr = tid >> 2;           // 0..63
    int lk = (tid & 3) * 4;      // 0,4,8,12
    // B-load mapping: thread -> (k-row, 8 consecutive cols)
    int bk = tid >> 4;           // 0..15
    int bc = (tid & 15) * 8;     // 0..120

    float rowsum[4] = {0.f, 0.f, 0.f, 0.f};

    for (int hc = 0; hc < H; hc += NT) {
        float decv[8], wo[8];
#pragma unroll
        for (int j = 0; j < 8; j++) {
            int h = hc + tx * 8 + j;
            decv[j] = g_decoded[b * H + h];
            wo[j]   = W_out[h];
        }
        float acc[4][8];
#pragma unroll
        for (int i = 0; i < 4; i++)
#pragma unroll
            for (int j = 0; j < 8; j++) acc[i][j] = 0.f;

        for (int k0 = 0; k0 < E; k0 += KC) {
            // issue global loads before the barrier (latency overlap)
            float4 av  = *(const float4*)(encBase + (long)lr * E + k0 + lk);
            float4 bv0 = *(const float4*)(W_enc + (long)(k0 + bk) * H + hc + bc);
            float4 bv1 = *(const float4*)(W_enc + (long)(k0 + bk) * H + hc + bc + 4);
            __syncthreads();   // previous iteration's smem reads done
            a_s[lk + 0][lr] = av.x;
            a_s[lk + 1][lr] = av.y;
            a_s[lk + 2][lr] = av.z;
            a_s[lk + 3][lr] = av.w;
            *(float4*)&b_s[bk][bc]     = bv0;
            *(float4*)&b_s[bk][bc + 4] = bv1;
            __syncthreads();
#pragma unroll
            for (int kk = 0; kk < KC; kk++) {
                float4 a4  = *(const float4*)&a_s[kk][ty * 4];
                float4 b40 = *(const float4*)&b_s[kk][tx * 8];
                float4 b41 = *(const float4*)&b_s[kk][tx * 8 + 4];
                float am[4] = {a4.x, a4.y, a4.z, a4.w};
                float bn[8] = {b40.x, b40.y, b40.z, b40.w,
                               b41.x, b41.y, b41.z, b41.w};
#pragma unroll
                for (int i = 0; i < 4; i++)
#pragma unroll
                    for (int j = 0; j < 8; j++)
                        acc[i][j] += am[i] * bn[j];
            }
        }
        // epilogue for this H chunk: tanh + dot with W_out
#pragma unroll
        for (int i = 0; i < 4; i++) {
            float s = 0.f;
#pragma unroll
            for (int j = 0; j < 8; j++)
                s += tanhf(acc[i][j] + decv[j]) * wo[j];
            rowsum[i] += s;
        }
    }
    // reduce over tx (16 lanes per row group, segmented shfl within warp)
#pragma unroll
    for (int i = 0; i < 4; i++) {
        float v = rowsum[i];
#pragma unroll
        for (int off = 8; off > 0; off >>= 1)
            v += __shfl_down_sync(0xffffffffu, v, off, 16);
        if (tx == 0) logits[base + ty * 4 + i] = v;
    }
}

// ---------------------------------------------------------------------------
// Kernel 3: masked softmax over S, in place on the probs region
// ---------------------------------------------------------------------------
__global__ void softmax_kernel(const int* __restrict__ mask,
                               float* __restrict__ probs) {
    int b = blockIdx.x;
    int t = threadIdx.x;  // 1024 threads, 4 elems each
    __shared__ float red[32];

    float l[4];
#pragma unroll
    for (int i = 0; i < 4; i++) {
        int s = t + i * 1024;
        float v = probs[(long)b * S + s];
        l[i] = (mask[(long)b * S + s] == 0) ? NEGV : v;
    }
    // block max
    float m = fmaxf(fmaxf(l[0], l[1]), fmaxf(l[2], l[3]));
#pragma unroll
    for (int off = 16; off > 0; off >>= 1)
        m = fmaxf(m, __shfl_xor_sync(0xffffffffu, m, off));
    if ((t & 31) == 0) red[t >> 5] = m;
    __syncthreads();
    if (t < 32) {
        float v = red[t];
#pragma unroll
        for (int off = 16; off > 0; off >>= 1)
            v = fmaxf(v, __shfl_xor_sync(0xffffffffu, v, off));
        red[t] = v;
    }
    __syncthreads();
    m = red[0];
    __syncthreads();

    float e[4];
    float sum = 0.f;
#pragma unroll
    for (int i = 0; i < 4; i++) {
        e[i] = expf(l[i] - m);
        sum += e[i];
    }
#pragma unroll
    for (int off = 16; off > 0; off >>= 1)
        sum += __shfl_xor_sync(0xffffffffu, sum, off);
    if ((t & 31) == 0) red[t >> 5] = sum;
    __syncthreads();
    if (t < 32) {
        float v = red[t];
#pragma unroll
        for (int off = 16; off > 0; off >>= 1)
            v += __shfl_xor_sync(0xffffffffu, v, off);
        red[t] = v;
    }
    __syncthreads();
    float inv = 1.f / red[0];
#pragma unroll
    for (int i = 0; i < 4; i++)
        probs[(long)b * S + t + i * 1024] = e[i] * inv;
}

// ---------------------------------------------------------------------------
// Kernel 4: partial attn over 128-row s-chunks (deterministic, no atomics)
// ---------------------------------------------------------------------------
__global__ void attn_part_kernel(const float* __restrict__ enc,
                                 const float* __restrict__ probs) {
    int sc = blockIdx.x & 31;
    int b  = blockIdx.x >> 5;
    int e  = threadIdx.x;  // 512 threads
    __shared__ float p_s[128];
    if (threadIdx.x < 128)
        p_s[threadIdx.x] = probs[(long)b * S + sc * 128 + threadIdx.x];
    __syncthreads();
    const float* encp = enc + ((long)b * S + (long)sc * 128) * E + e;
    float acc = 0.f;
#pragma unroll 4
    for (int s = 0; s < 128; s++) acc += p_s[s] * encp[(long)s * E];
    g_attn_part[((long)b * 32 + sc) * E + e] = acc;
}

// ---------------------------------------------------------------------------
// Kernel 5: fixed-order reduction of partials -> attn
// ---------------------------------------------------------------------------
__global__ void attn_reduce_kernel(float* __restrict__ attn) {
    int b = blockIdx.x;
    int e = threadIdx.x;
    float s = 0.f;
#pragma unroll
    for (int c = 0; c < 32; c++) s += g_attn_part[((long)b * 32 + c) * E + e];
    attn[b * E + e] = s;
}

// ---------------------------------------------------------------------------
extern "C" void kernel_launch(void* const* d_in, const int* in_sizes, int n_in,
                              void* d_out, int out_size) {
    const float* enc   = (const float*)d_in[0];  // [B,S,E]
    const float* dec   = (const float*)d_in[1];  // [B,D]
    const int*   mask  = (const int*)  d_in[2];  // [B,S]
    const float* W_enc = (const float*)d_in[3];  // [E,H]
    const float* W_dec = (const float*)d_in[4];  // [D,H]
    const float* W_out = (const float*)d_in[5];  // [H,1]

    float* attn  = (float*)d_out;        // [B,E] first (tuple order)
    float* probs = attn + B * E;         // [B,S] second; also used as logits

    decode_kernel<<<B, 512>>>(dec, W_dec);
    logits_kernel<<<B * (S / MT), 256>>>(enc, W_enc, W_out, probs);
    softmax_kernel<<<B, 1024>>>(mask, probs);
    attn_part_kernel<<<B * 32, 512>>>(enc, probs);
    attn_reduce_kernel<<<B, 512>>>(attn);
}

// round 3
// speedup vs baseline: 3.5423x; 3.5423x over previous
#include <cuda_runtime.h>
#include <math.h>
#include <cstdint>

#define B 64
#define S 4096
#define E 512
#define D 512
#define H 512
#define NEGV (-1.0e9f)

// ---------------------------------------------------------------------------
// Scratch (no cudaMalloc allowed)
// ---------------------------------------------------------------------------
__device__ float g_decoded[B * H];            // 128 KB
__device__ float g_attn_part[B * 32 * E];     // 4 MB
// W_enc^T split hi/lo, packed in mma-fragment order:
// float4 { hi(k), hi(k+4), lo(k), lo(k+4) } at index (k8*64 + n8)*32 + lane
__device__ float4 g_WB[64 * 64 * 32];         // 2 MB

// ---------------------------------------------------------------------------
// helpers
// ---------------------------------------------------------------------------
__device__ __forceinline__ uint32_t smem_u32(const void* p) {
    uint32_t a;
    asm("{ .reg .u64 t; cvta.to.shared.u64 t, %1; cvt.u32.u64 %0, t; }"
        : "=r"(a) : "l"(p));
    return a;
}
__device__ __forceinline__ float tf32_rnd(float x) {
    float r;
    asm("cvt.rna.tf32.f32 %0, %1;" : "=f"(r) : "f"(x));
    return r;
}
__device__ __forceinline__ float tanh_fast(float x) {
    // tanh(x) = 1 - 2/(exp(2x)+1), exp(2x) = 2^(2*log2(e)*x)
    float e;
    asm("ex2.approx.f32 %0, %1;" : "=f"(e) : "f"(x * 2.8853900817779268f));
    float r;
    asm("rcp.approx.f32 %0, %1;" : "=f"(r) : "f"(e + 1.0f));
    return fmaf(-2.0f, r, 1.0f);
}
#define MMA_TF32(d, a, b0, b1) \
    asm volatile( \
        "mma.sync.aligned.m16n8k8.row.col.f32.tf32.tf32.f32 " \
        "{%0,%1,%2,%3}, {%4,%5,%6,%7}, {%8,%9}, {%0,%1,%2,%3};" \
        : "+f"((d)[0]), "+f"((d)[1]), "+f"((d)[2]), "+f"((d)[3]) \
        : "r"((a)[0]), "r"((a)[1]), "r"((a)[2]), "r"((a)[3]), \
          "r"(b0), "r"(b1))

#define CP_ASYNC16(dst, src) \
    asm volatile("cp.async.ca.shared.global [%0], [%1], 16;" \
                 :: "r"(dst), "l"(src) : "memory")
#define CP_COMMIT()  asm volatile("cp.async.commit_group;" ::: "memory")
#define CP_WAIT(n)   asm volatile("cp.async.wait_group %0;" :: "n"(n) : "memory")

// A smem swizzle: float index for logical (row, col) in a 128x32 tile
__device__ __forceinline__ int a_idx(int r, int c) {
    return r * 32 + ((((c >> 2) ^ (r & 7)) << 2) | (c & 3));
}

// ---------------------------------------------------------------------------
// Kernel 0: W_enc [E,H] -> g_WB (transposed, tf32 hi/lo, fragment order)
// ---------------------------------------------------------------------------
__global__ void wsplit_kernel(const float* __restrict__ W_enc) {
    int idx = blockIdx.x * 256 + threadIdx.x;   // 131072 total
    int lane = idx & 31;
    int n8   = (idx >> 5) & 63;
    int k8   = idx >> 11;
    int k = k8 * 8 + (lane & 3);
    int n = n8 * 8 + (lane >> 2);
    float v0 = W_enc[k * H + n];
    float v1 = W_enc[(k + 4) * H + n];
    float h0 = tf32_rnd(v0), h1 = tf32_rnd(v1);
    float4 o;
    o.x = h0; o.y = h1;
    o.z = tf32_rnd(v0 - h0); o.w = tf32_rnd(v1 - h1);
    g_WB[idx] = o;
}

// ---------------------------------------------------------------------------
// Kernel 1: decoded[b,h] = dec[b,:] @ W_dec[:,h]
// ---------------------------------------------------------------------------
__global__ void decode_kernel(const float* __restrict__ dec,
                              const float* __restrict__ W_dec) {
    int b = blockIdx.x;
    int t = threadIdx.x;
    __shared__ float ds[D];
    ds[t] = dec[b * D + t];
    __syncthreads();
    float sum = 0.f;
#pragma unroll 8
    for (int d = 0; d < D; d++) sum += ds[d] * W_dec[d * H + t];
    g_decoded[b * H + t] = sum;
}

// ---------------------------------------------------------------------------
// Kernel 2: logits via mma.sync tf32x3
// grid = B*(S/128) = 2048 blocks, 256 threads (8 warps: 4 m-warps x 2 n-warps)
// block tile: M=128 rows, N processed in 4 chunks of 128 cols, K=512
// ---------------------------------------------------------------------------
__global__ void __launch_bounds__(256, 1)
logits_mma_kernel(const float* __restrict__ enc,
                  const float* __restrict__ W_out,
                  float* __restrict__ logits) {
    __shared__ float s_dec[H];
    __shared__ float s_wout[H];
    __shared__ float s_part[256];
    __shared__ __align__(128) float sA[2][128 * 32];

    int tid = threadIdx.x;
    int lane = tid & 31;
    int wid = tid >> 5;
    int mw = wid & 3;     // 0..3  -> rows mw*32..
    int nw = wid >> 2;    // 0..1  -> cols nw*64..

    int b  = blockIdx.x >> 5;
    int st = blockIdx.x & 31;
    long rowbase = (long)b * S + (long)st * 128;
    const float* encBase = enc + rowbase * E;

    for (int i = tid; i < H; i += 256) {
        s_dec[i]  = g_decoded[b * H + i];
        s_wout[i] = W_out[i];
    }

    const float4* gB = g_WB;
    float rowsum[4] = {0.f, 0.f, 0.f, 0.f};

    // staging helper (cp.async 16B x4 per thread = one 128x32 chunk)
    auto stageA = [&](int kc, int buf) {
#pragma unroll
        for (int it = 0; it < 4; it++) {
            int fidx = tid + it * 256;          // 0..1023 float4s
            int row = fidx >> 3;
            int kw  = fidx & 7;
            const float* src = encBase + (long)row * E + kc * 32 + kw * 4;
            uint32_t dst = smem_u32(&sA[buf][row * 32 + ((kw ^ (row & 7)) << 2)]);
            CP_ASYNC16(dst, src);
        }
        CP_COMMIT();
    };

    for (int nc = 0; nc < 4; nc++) {
        float acc[2][8][4];
#pragma unroll
        for (int mi = 0; mi < 2; mi++)
#pragma unroll
            for (int j = 0; j < 8; j++)
#pragma unroll
                for (int r = 0; r < 4; r++) acc[mi][j][r] = 0.f;

        int n8base = nc * 16 + nw * 8;

        // prime B for k8 = 0
        uint4 bc[8];
#pragma unroll
        for (int j = 0; j < 8; j++)
            bc[j] = *(const uint4*)&gB[(n8base + j) * 32 + lane];

        stageA(0, 0);

        for (int kc = 0; kc < 16; kc++) {
            if (kc < 15) { stageA(kc + 1, (kc + 1) & 1); CP_WAIT(1); }
            else         { CP_WAIT(0); }
            __syncthreads();
            const float* A = sA[kc & 1];

#pragma unroll
            for (int kk = 0; kk < 4; kk++) {
                int k8 = kc * 4 + kk;
                // prefetch B for next k8
                uint4 bn[8];
                int k8n = (k8 + 1 < 64) ? k8 + 1 : 63;
#pragma unroll
                for (int j = 0; j < 8; j++)
                    bn[j] = *(const uint4*)&gB[(k8n * 64 + n8base + j) * 32 + lane];

                // A fragments (hi & lo) for 2 m16 tiles
                uint32_t aH[2][4], aL[2][4];
#pragma unroll
                for (int mi = 0; mi < 2; mi++) {
                    int r0 = mw * 32 + mi * 16 + (lane >> 2);
                    int c0 = kk * 8 + (lane & 3);
                    float v0 = A[a_idx(r0,     c0)];
                    float v1 = A[a_idx(r0 + 8, c0)];
                    float v2 = A[a_idx(r0,     c0 + 4)];
                    float v3 = A[a_idx(r0 + 8, c0 + 4)];
                    float h0 = tf32_rnd(v0), h1 = tf32_rnd(v1);
                    float h2 = tf32_rnd(v2), h3 = tf32_rnd(v3);
                    aH[mi][0] = __float_as_uint(h0);
                    aH[mi][1] = __float_as_uint(h1);
                    aH[mi][2] = __float_as_uint(h2);
                    aH[mi][3] = __float_as_uint(h3);
                    aL[mi][0] = __float_as_uint(tf32_rnd(v0 - h0));
                    aL[mi][1] = __float_as_uint(tf32_rnd(v1 - h1));
                    aL[mi][2] = __float_as_uint(tf32_rnd(v2 - h2));
                    aL[mi][3] = __float_as_uint(tf32_rnd(v3 - h3));
                }

                // hi*hi
#pragma unroll
                for (int mi = 0; mi < 2; mi++)
#pragma unroll
                    for (int j = 0; j < 8; j++)
                        MMA_TF32(acc[mi][j], aH[mi], bc[j].x, bc[j].y);
                // lo*hi
#pragma unroll
                for (int mi = 0; mi < 2; mi++)
#pragma unroll
                    for (int j = 0; j < 8; j++)
                        MMA_TF32(acc[mi][j], aL[mi], bc[j].x, bc[j].y);
                // hi*lo
#pragma unroll
                for (int mi = 0; mi < 2; mi++)
#pragma unroll
                    for (int j = 0; j < 8; j++)
                        MMA_TF32(acc[mi][j], aH[mi], bc[j].z, bc[j].w);

#pragma unroll
                for (int j = 0; j < 8; j++) bc[j] = bn[j];
            }
            __syncthreads();
        }

        // epilogue for this N-chunk: tanh(acc + dec) * wout, into rowsum
#pragma unroll
        for (int mi = 0; mi < 2; mi++)
#pragma unroll
            for (int j = 0; j < 8; j++)
#pragma unroll
                for (int r = 0; r < 4; r++) {
                    int col = nc * 128 + nw * 64 + j * 8 + (lane & 3) * 2 + (r & 1);
                    float x = acc[mi][j][r] + s_dec[col];
                    rowsum[mi * 2 + (r >> 1)] += tanh_fast(x) * s_wout[col];
                }
    }

    // reduce rowsum: over lane&3 (shfl), then over nw (smem)
#pragma unroll
    for (int i = 0; i < 4; i++) {
        float v = rowsum[i];
        v += __shfl_xor_sync(0xffffffffu, v, 1);
        v += __shfl_xor_sync(0xffffffffu, v, 2);
        rowsum[i] = v;
    }
    if ((lane & 3) == 0) {
#pragma unroll
        for (int i = 0; i < 4; i++) {
            int row = mw * 32 + (i >> 1) * 16 + (lane >> 2) + (i & 1) * 8;
            s_part[nw * 128 + row] = rowsum[i];
        }
    }
    __syncthreads();
    if (tid < 128)
        logits[rowbase + tid] = s_part[tid] + s_part[128 + tid];
}

// ---------------------------------------------------------------------------
// Kernel 3: masked softmax over S, in place
// ---------------------------------------------------------------------------
__global__ void softmax_kernel(const int* __restrict__ mask,
                               float* __restrict__ probs) {
    int b = blockIdx.x;
    int t = threadIdx.x;
    __shared__ float red[32];
    float l[4];
#pragma unroll
    for (int i = 0; i < 4; i++) {
        int s = t + i * 1024;
        float v = probs[(long)b * S + s];
        l[i] = (mask[(long)b * S + s] == 0) ? NEGV : v;
    }
    float m = fmaxf(fmaxf(l[0], l[1]), fmaxf(l[2], l[3]));
#pragma unroll
    for (int off = 16; off > 0; off >>= 1)
        m = fmaxf(m, __shfl_xor_sync(0xffffffffu, m, off));
    if ((t & 31) == 0) red[t >> 5] = m;
    __syncthreads();
    if (t < 32) {
        float v = red[t];
#pragma unroll
        for (int off = 16; off > 0; off >>= 1)
            v = fmaxf(v, __shfl_xor_sync(0xffffffffu, v, off));
        red[t] = v;
    }
    __syncthreads();
    m = red[0];
    __syncthreads();
    float e[4];
    float sum = 0.f;
#pragma unroll
    for (int i = 0; i < 4; i++) { e[i] = expf(l[i] - m); sum += e[i]; }
#pragma unroll
    for (int off = 16; off > 0; off >>= 1)
        sum += __shfl_xor_sync(0xffffffffu, sum, off);
    if ((t & 31) == 0) red[t >> 5] = sum;
    __syncthreads();
    if (t < 32) {
        float v = red[t];
#pragma unroll
        for (int off = 16; off > 0; off >>= 1)
            v += __shfl_xor_sync(0xffffffffu, v, off);
        red[t] = v;
    }
    __syncthreads();
    float inv = 1.f / red[0];
#pragma unroll
    for (int i = 0; i < 4; i++)
        probs[(long)b * S + t + i * 1024] = e[i] * inv;
}

// ---------------------------------------------------------------------------
// Kernel 4: partial attn over 128-row s-chunks
// ---------------------------------------------------------------------------
__global__ void attn_part_kernel(const float* __restrict__ enc,
                                 const float* __restrict__ probs) {
    int sc = blockIdx.x & 31;
    int b  = blockIdx.x >> 5;
    int e  = threadIdx.x;
    __shared__ float p_s[128];
    if (threadIdx.x < 128)
        p_s[threadIdx.x] = probs[(long)b * S + sc * 128 + threadIdx.x];
    __syncthreads();
    const float* encp = enc + ((long)b * S + (long)sc * 128) * E + e;
    float acc = 0.f;
#pragma unroll 8
    for (int s = 0; s < 128; s++) acc += p_s[s] * encp[(long)s * E];
    g_attn_part[((long)b * 32 + sc) * E + e] = acc;
}

// ---------------------------------------------------------------------------
// Kernel 5: fixed-order reduction -> attn
// ---------------------------------------------------------------------------
__global__ void attn_reduce_kernel(float* __restrict__ attn) {
    int b = blockIdx.x;
    int e = threadIdx.x;
    float s = 0.f;
#pragma unroll
    for (int c = 0; c < 32; c++) s += g_attn_part[((long)b * 32 + c) * E + e];
    attn[b * E + e] = s;
}

// ---------------------------------------------------------------------------
extern "C" void kernel_launch(void* const* d_in, const int* in_sizes, int n_in,
                              void* d_out, int out_size) {
    const float* enc   = (const float*)d_in[0];
    const float* dec   = (const float*)d_in[1];
    const int*   mask  = (const int*)  d_in[2];
    const float* W_enc = (const float*)d_in[3];
    const float* W_dec = (const float*)d_in[4];
    const float* W_out = (const float*)d_in[5];

    float* attn  = (float*)d_out;       // [B,E]
    float* probs = attn + B * E;        // [B,S] (logits written in place)

    wsplit_kernel<<<512, 256>>>(W_enc);
    decode_kernel<<<B, 512>>>(dec, W_dec);
    logits_mma_kernel<<<B * (S / 128), 256>>>(enc, W_out, probs);
    softmax_kernel<<<B, 1024>>>(mask, probs);
    attn_part_kernel<<<B * 32, 512>>>(enc, probs);
    attn_reduce_kernel<<<B, 512>>>(attn);
}